// round 2
// baseline (speedup 1.0000x reference)
#include <cuda_runtime.h>
#include <math.h>

#define Bdim 4
#define Tdim 1024
#define Cdim 1024
#define Hdim 16
#define HDdim 64
#define BHdim 64

// Scratch (allocation-free: __device__ globals)
__device__ float g_Q[Bdim*Hdim*Tdim*HDdim];   // 16 MB  [bh][t][d]
__device__ float g_K[Bdim*Hdim*Tdim*HDdim];   // 16 MB
__device__ float g_V[Bdim*Hdim*Tdim*HDdim];   // 16 MB
__device__ float g_Y[Bdim*Tdim*Cdim];         // 16 MB  [b][t][c]
__device__ float g_P[67108864];               // 256 MB [bh][j][i] : E[h,i-j]·k_j

// ---------------------------------------------------------------------------
// Generic fp32 SGEMM, 128x128 tile, BK=8, 256 threads, 8x8 per thread.
// mode 0: C = A@B + bias, scatter-store into g_Q/g_K/g_V ((b,h,t,d) layout)
// mode 1: A := g_Y,  C = g_Y@B + bias -> Cout (row-major)
// ---------------------------------------------------------------------------
__global__ void __launch_bounds__(256) sgemm_kernel(
    const float* __restrict__ A, const float* __restrict__ Bw,
    const float* __restrict__ bias, float* __restrict__ Cout,
    int M, int N, int K, int mode)
{
    __shared__ float As[8][128];
    __shared__ float Bs[8][128];

    const float* Ap = (mode == 1) ? g_Y : A;

    const int tid  = threadIdx.x;
    const int m0   = blockIdx.y * 128;
    const int n0   = blockIdx.x * 128;
    const int tRow = (tid / 16) * 8;
    const int tCol = (tid % 16) * 8;

    const int aRow = tid / 2;
    const int aCol = (tid % 2) * 4;
    const int bRow = tid / 32;
    const int bCol = (tid % 32) * 4;

    const float* Aptr = Ap + (size_t)(m0 + aRow) * K + aCol;
    const float* Bptr = Bw + (size_t)bRow * N + n0 + bCol;

    float acc[8][8];
    #pragma unroll
    for (int i = 0; i < 8; i++)
        #pragma unroll
        for (int j = 0; j < 8; j++) acc[i][j] = 0.f;

    for (int kk = 0; kk < K; kk += 8) {
        float4 av = *(const float4*)(Aptr + kk);
        float4 bv = *(const float4*)(Bptr + (size_t)kk * N);
        As[aCol+0][aRow] = av.x;
        As[aCol+1][aRow] = av.y;
        As[aCol+2][aRow] = av.z;
        As[aCol+3][aRow] = av.w;
        *(float4*)&Bs[bRow][bCol] = bv;
        __syncthreads();

        #pragma unroll
        for (int k = 0; k < 8; k++) {
            float ra[8], rb[8];
            *(float4*)&ra[0] = *(const float4*)&As[k][tRow];
            *(float4*)&ra[4] = *(const float4*)&As[k][tRow + 4];
            *(float4*)&rb[0] = *(const float4*)&Bs[k][tCol];
            *(float4*)&rb[4] = *(const float4*)&Bs[k][tCol + 4];
            #pragma unroll
            for (int i = 0; i < 8; i++)
                #pragma unroll
                for (int j = 0; j < 8; j++)
                    acc[i][j] = fmaf(ra[i], rb[j], acc[i][j]);
        }
        __syncthreads();
    }

    if (mode == 0) {
        // scatter to Q/K/V in (b,h,t,d) layout
        #pragma unroll
        for (int i = 0; i < 8; i++) {
            int m = m0 + tRow + i;
            int b = m >> 10, t = m & 1023;
            #pragma unroll
            for (int j = 0; j < 8; j++) {
                int n = n0 + tCol + j;
                float v = acc[i][j] + bias[n];
                int which = n >> 10;
                int c = n & 1023;
                int h = c >> 6, d = c & 63;
                float* dst = (which == 0) ? g_Q : ((which == 1) ? g_K : g_V);
                dst[(size_t)(((b * 16 + h) << 10) + t) * 64 + d] = v;
            }
        }
    } else {
        #pragma unroll
        for (int i = 0; i < 8; i++) {
            int m = m0 + tRow + i;
            #pragma unroll
            for (int j = 0; j < 8; j++) {
                int n = n0 + tCol + j;
                Cout[(size_t)m * N + n] = acc[i][j] + bias[n];
            }
        }
    }
}

// ---------------------------------------------------------------------------
// Relative-position table: g_P[bh][j][i] = sum_d E[h, i-j, d] * K[bh, j, d]
// GEMM tile computes C[j][r] = K[j]·E[r], stored shifted at column i = j + r.
// Only i < T needed (causal). Tiles with j0+r0 >= T fully pruned.
// ---------------------------------------------------------------------------
__global__ void __launch_bounds__(256) pos_gemm_kernel(const float* __restrict__ rel)
{
    const int j0 = blockIdx.x * 64;
    const int r0 = blockIdx.y * 64;
    if (j0 + r0 >= Tdim) return;
    const int bh = blockIdx.z;
    const int h  = bh & 15;

    __shared__ float Ks[64][65];
    __shared__ float Es[64][65];

    const float* Kg = g_K + (size_t)bh * Tdim * 64 + (size_t)j0 * 64;
    const float* Eg = rel + (size_t)h  * Tdim * 64 + (size_t)r0 * 64;

    const int tid = threadIdx.x;
    #pragma unroll
    for (int p = 0; p < 4; p++) {
        int f4  = p * 256 + tid;
        int row = f4 >> 4;
        int c   = (f4 & 15) * 4;
        float4 kv = *(const float4*)(Kg + row * 64 + c);
        Ks[row][c+0] = kv.x; Ks[row][c+1] = kv.y; Ks[row][c+2] = kv.z; Ks[row][c+3] = kv.w;
        float4 ev = *(const float4*)(Eg + row * 64 + c);
        Es[row][c+0] = ev.x; Es[row][c+1] = ev.y; Es[row][c+2] = ev.z; Es[row][c+3] = ev.w;
    }
    __syncthreads();

    const int ty = tid / 16, tx = tid % 16;
    float acc[4][4];
    #pragma unroll
    for (int a = 0; a < 4; a++)
        #pragma unroll
        for (int b = 0; b < 4; b++) acc[a][b] = 0.f;

    #pragma unroll 4
    for (int d = 0; d < 64; d++) {
        float rj[4], rr[4];
        #pragma unroll
        for (int a = 0; a < 4; a++) rj[a] = Ks[4*ty + a][d];
        #pragma unroll
        for (int b = 0; b < 4; b++) rr[b] = Es[4*tx + b][d];
        #pragma unroll
        for (int a = 0; a < 4; a++)
            #pragma unroll
            for (int b = 0; b < 4; b++)
                acc[a][b] = fmaf(rj[a], rr[b], acc[a][b]);
    }

    float* outb = g_P + (size_t)bh * (Tdim * Tdim);
    #pragma unroll
    for (int a = 0; a < 4; a++) {
        int j = j0 + 4*ty + a;
        float* outr = outb + (size_t)j * Tdim;
        #pragma unroll
        for (int b = 0; b < 4; b++) {
            int i = j + r0 + 4*tx + b;
            if (i < Tdim) outr[i] = acc[a][b];
        }
    }
}

// ---------------------------------------------------------------------------
// Fused causal flash attention with precomputed relative-position bias.
// One block = one (bh, 64-row query tile). 256 threads, 4x4 micro-tile.
// smem (dynamic, 66.5 KB): Qs, Ks, Vs, Ps each [64][65].
// Ps double-duty: bias tile on load, probability tile after softmax.
// NOTE: bias is read TRANSPOSED (thread (ty,tx) reads Ps[4tx+c][4ty+a]) while
// probabilities are written untransposed (Ps[4ty+a][4tx+c]) — those are the
// SAME addresses owned by DIFFERENT threads, so a barrier between the bias
// read and the probability store is mandatory (this was the round-1 bug).
// ---------------------------------------------------------------------------
__global__ void __launch_bounds__(256) flash_kernel(const float* __restrict__ unused)
{
    extern __shared__ float sm[];
    float* Qs = sm;
    float* Ks = Qs + 64 * 65;
    float* Vs = Ks + 64 * 65;
    float* Ps = Vs + 64 * 65;

    const int it = (int)gridDim.x - 1 - (int)blockIdx.x;  // heavy tiles first
    const int i0 = it * 64;
    const int bh = blockIdx.y;
    const int b  = bh >> 4, h = bh & 15;

    const int tid = threadIdx.x;
    const int ty  = tid / 16, tx = tid % 16;

    // load Q tile
    {
        const float* Qg = g_Q + ((size_t)bh * Tdim + i0) * 64;
        #pragma unroll
        for (int p = 0; p < 4; p++) {
            int f4  = p * 256 + tid;
            int row = f4 >> 4;
            int c   = (f4 & 15) * 4;
            float4 v = *(const float4*)(Qg + row * 64 + c);
            Qs[row*65 + c+0] = v.x; Qs[row*65 + c+1] = v.y;
            Qs[row*65 + c+2] = v.z; Qs[row*65 + c+3] = v.w;
        }
    }

    float mr[4], lr[4], acc[4][4];
    #pragma unroll
    for (int a = 0; a < 4; a++) {
        mr[a] = -1e30f; lr[a] = 0.f;
        #pragma unroll
        for (int c = 0; c < 4; c++) acc[a][c] = 0.f;
    }

    for (int j0 = 0; j0 <= i0; j0 += 64) {
        __syncthreads();   // previous AV done before overwriting K/V/Ps

        const float* Kg = g_K + ((size_t)bh * Tdim + j0) * 64;
        const float* Vg = g_V + ((size_t)bh * Tdim + j0) * 64;
        const float* Pg = g_P + (size_t)bh * (Tdim * Tdim) + (size_t)j0 * Tdim + i0;
        #pragma unroll
        for (int p = 0; p < 4; p++) {
            int f4  = p * 256 + tid;
            int row = f4 >> 4;
            int c   = (f4 & 15) * 4;
            float4 kv = *(const float4*)(Kg + row * 64 + c);
            Ks[row*65 + c+0] = kv.x; Ks[row*65 + c+1] = kv.y;
            Ks[row*65 + c+2] = kv.z; Ks[row*65 + c+3] = kv.w;
            float4 vv = *(const float4*)(Vg + row * 64 + c);
            Vs[row*65 + c+0] = vv.x; Vs[row*65 + c+1] = vv.y;
            Vs[row*65 + c+2] = vv.z; Vs[row*65 + c+3] = vv.w;
            float4 pv = *(const float4*)(Pg + (size_t)row * Tdim + c);
            Ps[row*65 + c+0] = pv.x; Ps[row*65 + c+1] = pv.y;
            Ps[row*65 + c+2] = pv.z; Ps[row*65 + c+3] = pv.w;
        }
        __syncthreads();

        // S = Q K^T
        float s[4][4];
        #pragma unroll
        for (int a = 0; a < 4; a++)
            #pragma unroll
            for (int c = 0; c < 4; c++) s[a][c] = 0.f;

        #pragma unroll 4
        for (int d = 0; d < 64; d++) {
            float rq[4], rk[4];
            #pragma unroll
            for (int a = 0; a < 4; a++) rq[a] = Qs[(4*ty + a)*65 + d];
            #pragma unroll
            for (int c = 0; c < 4; c++) rk[c] = Ks[(4*tx + c)*65 + d];
            #pragma unroll
            for (int a = 0; a < 4; a++)
                #pragma unroll
                for (int c = 0; c < 4; c++)
                    s[a][c] = fmaf(rq[a], rk[c], s[a][c]);
        }

        // bias (Ps holds Ppos[j][i], read transposed) + scale + causal mask
        const bool diag = (j0 == i0);
        #pragma unroll
        for (int a = 0; a < 4; a++) {
            #pragma unroll
            for (int c = 0; c < 4; c++) {
                float bias = Ps[(4*tx + c)*65 + (4*ty + a)];
                float v = (s[a][c] + bias) * 0.125f;
                if (diag && (4*tx + c) > (4*ty + a)) v = -1e30f;
                s[a][c] = v;
            }
        }

        // === barrier: every thread must finish READING bias from Ps before
        // any thread overwrites Ps with probabilities (transpose race fix) ===
        __syncthreads();

        // online softmax (row groups of 16 lanes share a ty)
        #pragma unroll
        for (int a = 0; a < 4; a++) {
            float rmax = s[a][0];
            rmax = fmaxf(rmax, s[a][1]);
            rmax = fmaxf(rmax, s[a][2]);
            rmax = fmaxf(rmax, s[a][3]);
            #pragma unroll
            for (int off = 8; off >= 1; off >>= 1)
                rmax = fmaxf(rmax, __shfl_xor_sync(0xffffffffu, rmax, off));
            float newm = fmaxf(mr[a], rmax);
            float corr = __expf(mr[a] - newm);
            float rsum = 0.f;
            #pragma unroll
            for (int c = 0; c < 4; c++) {
                s[a][c] = __expf(s[a][c] - newm);
                rsum += s[a][c];
            }
            #pragma unroll
            for (int off = 8; off >= 1; off >>= 1)
                rsum += __shfl_xor_sync(0xffffffffu, rsum, off);
            lr[a] = lr[a] * corr + rsum;
            mr[a] = newm;
            #pragma unroll
            for (int c = 0; c < 4; c++) acc[a][c] *= corr;
        }

        // store probabilities
        #pragma unroll
        for (int a = 0; a < 4; a++)
            #pragma unroll
            for (int c = 0; c < 4; c++)
                Ps[(4*ty + a)*65 + (4*tx + c)] = s[a][c];
        __syncthreads();

        // acc += P @ V
        #pragma unroll 4
        for (int jj = 0; jj < 64; jj++) {
            float rp[4], rv[4];
            #pragma unroll
            for (int a = 0; a < 4; a++) rp[a] = Ps[(4*ty + a)*65 + jj];
            #pragma unroll
            for (int c = 0; c < 4; c++) rv[c] = Vs[jj*65 + 4*tx + c];
            #pragma unroll
            for (int a = 0; a < 4; a++)
                #pragma unroll
                for (int c = 0; c < 4; c++)
                    acc[a][c] = fmaf(rp[a], rv[c], acc[a][c]);
        }
    }

    // write Y[b][t][h*64 + d]
    float* Yg = g_Y + ((size_t)b * Tdim + i0) * Cdim + h * 64;
    #pragma unroll
    for (int a = 0; a < 4; a++) {
        float inv = 1.f / lr[a];
        #pragma unroll
        for (int c = 0; c < 4; c++)
            Yg[(size_t)(4*ty + a) * Cdim + 4*tx + c] = acc[a][c] * inv;
    }
}

// ---------------------------------------------------------------------------
extern "C" void kernel_launch(void* const* d_in, const int* in_sizes, int n_in,
                              void* d_out, int out_size)
{
    const float* x      = (const float*)d_in[0];
    const float* W_attn = (const float*)d_in[1];
    const float* b_attn = (const float*)d_in[2];
    const float* W_proj = (const float*)d_in[3];
    const float* b_proj = (const float*)d_in[4];
    const float* rel    = (const float*)d_in[5];
    float* out = (float*)d_out;

    // 1) QKV = x @ W_attn + b_attn, scattered into (b,h,t,d)
    sgemm_kernel<<<dim3(3072/128, 4096/128), 256>>>(
        x, W_attn, b_attn, nullptr, 4096, 3072, 1024, 0);

    // 2) relative-position table Ppos[bh][j][i]
    pos_gemm_kernel<<<dim3(16, 16, BHdim), 256>>>(rel);

    // 3) fused causal flash attention
    cudaFuncSetAttribute(flash_kernel,
                         cudaFuncAttributeMaxDynamicSharedMemorySize, 4 * 64 * 65 * 4);
    flash_kernel<<<dim3(16, BHdim), 256, 4 * 64 * 65 * 4>>>(nullptr);

    // 4) out = Y @ W_proj + b_proj
    sgemm_kernel<<<dim3(1024/128, 4096/128), 256>>>(
        nullptr, W_proj, b_proj, out, 4096, 1024, 1024, 1);
}

// round 6
// speedup vs baseline: 1.3587x; 1.3587x over previous
#include <cuda_runtime.h>
#include <cuda_bf16.h>
#include <mma.h>
#include <cstdint>
#include <math.h>

using namespace nvcuda;

#define Bdim 4
#define Tdim 1024
#define Cdim 1024
#define Hdim 16
#define HDdim 64
#define BHdim 64

// Scratch (allocation-free: __device__ globals).
// NEVER passed as kernel args from host — selected inside device code.
__device__ float g_Q[Bdim*Hdim*Tdim*HDdim];   // 16 MB  [bh][t][d]
__device__ float g_K[Bdim*Hdim*Tdim*HDdim];   // 16 MB
__device__ float g_V[Bdim*Hdim*Tdim*HDdim];   // 16 MB
__device__ float g_Y[Bdim*Tdim*Cdim];         // 16 MB  [b][t][c]
__device__ float g_P[67108864];               // 256 MB [bh][j][i] : E[h,i-j]·k_j
// bf16-split operands
__device__ __nv_bfloat16 g_xhi[4194304], g_xlo[4194304];   // x split        [4096][1024]
__device__ __nv_bfloat16 g_Wah[3145728], g_Wal[3145728];   // W_attn^T split [3072][1024]
__device__ __nv_bfloat16 g_Wph[1048576], g_Wpl[1048576];   // W_proj^T split [1024][1024]
__device__ __nv_bfloat16 g_Yhi[4194304], g_Ylo[4194304];   // Y split        [4096][1024]

// ---------------------------------------------------------------------------
__device__ __forceinline__ uint32_t smem_u32(const void* p) {
    uint32_t a;
    asm("{ .reg .u64 t; cvta.to.shared.u64 t, %1; cvt.u32.u64 %0, t; }" : "=r"(a) : "l"(p));
    return a;
}
__device__ __forceinline__ void cp16(uint32_t dst, const void* src) {
    asm volatile("cp.async.cg.shared.global [%0], [%1], 16;" :: "r"(dst), "l"(src) : "memory");
}

// ---------------------------------------------------------------------------
// prep: bf16 hi/lo split (dst selected device-side), transpose+split weights
// ---------------------------------------------------------------------------
__global__ void __launch_bounds__(256) split_kernel(
    const float* __restrict__ s_in, int dst_which, int n)
{
    // dst_which 0: (g_xhi, g_xlo) from s_in ; 1: (g_Yhi, g_Ylo) from g_Y
    const float* s = (dst_which == 0) ? s_in : g_Y;
    __nv_bfloat16* hi = (dst_which == 0) ? g_xhi : g_Yhi;
    __nv_bfloat16* lo = (dst_which == 0) ? g_xlo : g_Ylo;
    for (int i = blockIdx.x * blockDim.x + threadIdx.x; i < n; i += gridDim.x * blockDim.x) {
        float x = s[i];
        __nv_bfloat16 h = __float2bfloat16(x);
        hi[i] = h;
        lo[i] = __float2bfloat16(x - __bfloat162float(h));
    }
}

// W[K][N] -> T[N][K] hi/lo (bf16); dst selected device-side
__global__ void __launch_bounds__(256) transpose_split_kernel(
    const float* __restrict__ W, int which, int K, int N)
{
    __nv_bfloat16* Th = (which == 0) ? g_Wah : g_Wph;
    __nv_bfloat16* Tl = (which == 0) ? g_Wal : g_Wpl;
    __shared__ float t[32][33];
    int n0 = blockIdx.x * 32, k0 = blockIdx.y * 32;
    int tx = threadIdx.x & 31, ty = threadIdx.x >> 5;
    #pragma unroll
    for (int i = 0; i < 32; i += 8)
        t[ty + i][tx] = W[(size_t)(k0 + ty + i) * N + n0 + tx];
    __syncthreads();
    #pragma unroll
    for (int i = 0; i < 32; i += 8) {
        float v = t[tx][ty + i];
        __nv_bfloat16 h = __float2bfloat16(v);
        size_t o = (size_t)(n0 + ty + i) * K + k0 + tx;
        Th[o] = h;
        Tl[o] = __float2bfloat16(v - __bfloat162float(h));
    }
}

// ---------------------------------------------------------------------------
// bf16 3-product WMMA GEMM. C[m][n] = sum_k A[m][k]*B[n][k]  (B = W^T)
// 128x128 CTA tile, 8 warps (warp_m = wid&1 -> 64 rows, warp_n = wid>>1 -> 32 cols)
// K-chunk 32, double-buffered cp.async. Operands selected device-side by `sel`.
// sel 0: A=(g_xhi,g_xlo) B=(g_Wah,g_Wal)   sel 1: A=(g_Yhi,g_Ylo) B=(g_Wph,g_Wpl)
// Epilogue: frags -> smem staging (128x132 f32) -> bias + scatter/store.
// mode 0: scatter into g_Q/g_K/g_V (round-2 verified logic). mode 1: Cout.
// ---------------------------------------------------------------------------
#define LDH 40                    // smem row stride in halves
#define MATH (128*LDH)            // halves per matrix (5120)
#define MATB (MATH*2)             // bytes per matrix (10240)
#define STGB (4*MATB)             // bytes per stage (40960)
#define SMEM_GEMM (2*STGB)        // 81920

__device__ __forceinline__ void ld_mat(uint32_t dstbase, const __nv_bfloat16* __restrict__ src,
                                       int r0, int k0, int K, int tid)
{
    #pragma unroll
    for (int j = 0; j < 2; j++) {
        int idx = tid + j * 256;          // 0..511
        int row = idx >> 2, c = idx & 3;  // row 0..127, 16B chunk 0..3
        cp16(dstbase + row * 80 + c * 16, src + (size_t)(r0 + row) * K + k0 + c * 8);
    }
}

#define LOADSTAGE(t_, s_) do {                                         \
    uint32_t b_ = sb + (s_) * STGB;                                    \
    ld_mat(b_,            Ah, m0, (t_) * 32, K, tid);                  \
    ld_mat(b_ +     MATB, Al, m0, (t_) * 32, K, tid);                  \
    ld_mat(b_ + 2 * MATB, Bh, n0, (t_) * 32, K, tid);                  \
    ld_mat(b_ + 3 * MATB, Bl, n0, (t_) * 32, K, tid);                  \
    asm volatile("cp.async.commit_group;" ::: "memory");               \
} while (0)

__global__ void __launch_bounds__(256) gemm_bf16_kernel(
    int sel, const float* __restrict__ bias, float* __restrict__ Cout,
    int K, int mode, int ldc)
{
    extern __shared__ __align__(128) char smraw[];
    __nv_bfloat16* sh = (__nv_bfloat16*)smraw;
    float* Csm = (float*)smraw;
    uint32_t sb = smem_u32(smraw);

    // device-side operand resolution (host must NOT pass __device__ symbols)
    const __nv_bfloat16* Ah = (sel == 0) ? g_xhi : g_Yhi;
    const __nv_bfloat16* Al = (sel == 0) ? g_xlo : g_Ylo;
    const __nv_bfloat16* Bh = (sel == 0) ? g_Wah : g_Wph;
    const __nv_bfloat16* Bl = (sel == 0) ? g_Wal : g_Wpl;

    const int tid = threadIdx.x, wid = tid >> 5;
    const int warp_m = wid & 1, warp_n = wid >> 1;  // 2 x 4 warp grid
    const int m0 = blockIdx.y * 128;
    const int n0 = blockIdx.x * 128;
    const int NT = K >> 5;

    wmma::fragment<wmma::accumulator, 16, 16, 16, float> facc[4][2];
    #pragma unroll
    for (int mi = 0; mi < 4; mi++)
        #pragma unroll
        for (int ni = 0; ni < 2; ni++)
            wmma::fill_fragment(facc[mi][ni], 0.0f);

    LOADSTAGE(0, 0);

    for (int t = 0; t < NT; t++) {
        if (t + 1 < NT) {
            LOADSTAGE(t + 1, (t + 1) & 1);
            asm volatile("cp.async.wait_group 1;" ::: "memory");
        } else {
            asm volatile("cp.async.wait_group 0;" ::: "memory");
        }
        __syncthreads();

        const __nv_bfloat16* Ahs = sh + (size_t)(t & 1) * (4 * MATH);
        const __nv_bfloat16* Als = Ahs + MATH;
        const __nv_bfloat16* Bhs = Ahs + 2 * MATH;
        const __nv_bfloat16* Bls = Ahs + 3 * MATH;

        #pragma unroll
        for (int kt = 0; kt < 32; kt += 16) {
            wmma::fragment<wmma::matrix_a, 16, 16, 16, __nv_bfloat16, wmma::row_major> fah[4], fal[4];
            wmma::fragment<wmma::matrix_b, 16, 16, 16, __nv_bfloat16, wmma::col_major> fbh[2], fbl[2];
            #pragma unroll
            for (int mi = 0; mi < 4; mi++) {
                int mrow = warp_m * 64 + mi * 16;
                wmma::load_matrix_sync(fah[mi], Ahs + mrow * LDH + kt, LDH);
                wmma::load_matrix_sync(fal[mi], Als + mrow * LDH + kt, LDH);
            }
            #pragma unroll
            for (int ni = 0; ni < 2; ni++) {
                int nrow = warp_n * 32 + ni * 16;
                wmma::load_matrix_sync(fbh[ni], Bhs + nrow * LDH + kt, LDH);
                wmma::load_matrix_sync(fbl[ni], Bls + nrow * LDH + kt, LDH);
            }
            #pragma unroll
            for (int mi = 0; mi < 4; mi++)
                #pragma unroll
                for (int ni = 0; ni < 2; ni++) {
                    wmma::mma_sync(facc[mi][ni], fah[mi], fbh[ni], facc[mi][ni]);
                    wmma::mma_sync(facc[mi][ni], fah[mi], fbl[ni], facc[mi][ni]);
                    wmma::mma_sync(facc[mi][ni], fal[mi], fbh[ni], facc[mi][ni]);
                }
        }
        __syncthreads();
    }

    // epilogue: frags -> smem (128 x 132 f32), then bias + store/scatter
    #pragma unroll
    for (int mi = 0; mi < 4; mi++)
        #pragma unroll
        for (int ni = 0; ni < 2; ni++)
            wmma::store_matrix_sync(
                Csm + (warp_m * 64 + mi * 16) * 132 + warp_n * 32 + ni * 16,
                facc[mi][ni], 132, wmma::mem_row_major);
    __syncthreads();

    for (int e = tid; e < 128 * 128; e += 256) {
        int mr = e >> 7, nc = e & 127;
        int m = m0 + mr, n = n0 + nc;
        float v = Csm[mr * 132 + nc] + bias[n];
        if (mode == 0) {
            int which = n >> 10;
            int cc = n & 1023;
            int h = cc >> 6, d = cc & 63;
            float* dst = (which == 0) ? g_Q : ((which == 1) ? g_K : g_V);
            int bb = m >> 10, tt = m & 1023;
            dst[(size_t)(((bb * 16 + h) << 10) + tt) * 64 + d] = v;
        } else {
            Cout[(size_t)m * ldc + n] = v;
        }
    }
}

// ---------------------------------------------------------------------------
// Relative-position table: g_P[bh][j][i] = sum_d E[h, i-j, d] * K[bh, j, d]
// ---------------------------------------------------------------------------
__global__ void __launch_bounds__(256) pos_gemm_kernel(const float* __restrict__ rel)
{
    const int j0 = blockIdx.x * 64;
    const int r0 = blockIdx.y * 64;
    if (j0 + r0 >= Tdim) return;
    const int bh = blockIdx.z;
    const int h  = bh & 15;

    __shared__ float Ks[64][65];
    __shared__ float Es[64][65];

    const float* Kg = g_K + (size_t)bh * Tdim * 64 + (size_t)j0 * 64;
    const float* Eg = rel + (size_t)h  * Tdim * 64 + (size_t)r0 * 64;

    const int tid = threadIdx.x;
    #pragma unroll
    for (int p = 0; p < 4; p++) {
        int f4  = p * 256 + tid;
        int row = f4 >> 4;
        int c   = (f4 & 15) * 4;
        float4 kv = *(const float4*)(Kg + row * 64 + c);
        Ks[row][c+0] = kv.x; Ks[row][c+1] = kv.y; Ks[row][c+2] = kv.z; Ks[row][c+3] = kv.w;
        float4 ev = *(const float4*)(Eg + row * 64 + c);
        Es[row][c+0] = ev.x; Es[row][c+1] = ev.y; Es[row][c+2] = ev.z; Es[row][c+3] = ev.w;
    }
    __syncthreads();

    const int ty = tid / 16, tx = tid % 16;
    float acc[4][4];
    #pragma unroll
    for (int a = 0; a < 4; a++)
        #pragma unroll
        for (int b = 0; b < 4; b++) acc[a][b] = 0.f;

    #pragma unroll 4
    for (int d = 0; d < 64; d++) {
        float rj[4], rr[4];
        #pragma unroll
        for (int a = 0; a < 4; a++) rj[a] = Ks[4*ty + a][d];
        #pragma unroll
        for (int b = 0; b < 4; b++) rr[b] = Es[4*tx + b][d];
        #pragma unroll
        for (int a = 0; a < 4; a++)
            #pragma unroll
            for (int b = 0; b < 4; b++)
                acc[a][b] = fmaf(rj[a], rr[b], acc[a][b]);
    }

    float* outb = g_P + (size_t)bh * (Tdim * Tdim);
    #pragma unroll
    for (int a = 0; a < 4; a++) {
        int j = j0 + 4*ty + a;
        float* outr = outb + (size_t)j * Tdim;
        #pragma unroll
        for (int b = 0; b < 4; b++) {
            int i = j + r0 + 4*tx + b;
            if (i < Tdim) outr[i] = acc[a][b];
        }
    }
}

// ---------------------------------------------------------------------------
// Fused causal flash attention with precomputed relative-position bias.
// ---------------------------------------------------------------------------
__global__ void __launch_bounds__(256) flash_kernel(const float* __restrict__ unused)
{
    extern __shared__ float smf[];
    float* Qs = smf;
    float* Ks = Qs + 64 * 65;
    float* Vs = Ks + 64 * 65;
    float* Ps = Vs + 64 * 65;

    const int it = (int)gridDim.x - 1 - (int)blockIdx.x;  // heavy tiles first
    const int i0 = it * 64;
    const int bh = blockIdx.y;
    const int b  = bh >> 4, h = bh & 15;

    const int tid = threadIdx.x;
    const int ty  = tid / 16, tx = tid % 16;

    {
        const float* Qg = g_Q + ((size_t)bh * Tdim + i0) * 64;
        #pragma unroll
        for (int p = 0; p < 4; p++) {
            int f4  = p * 256 + tid;
            int row = f4 >> 4;
            int c   = (f4 & 15) * 4;
            float4 v = *(const float4*)(Qg + row * 64 + c);
            Qs[row*65 + c+0] = v.x; Qs[row*65 + c+1] = v.y;
            Qs[row*65 + c+2] = v.z; Qs[row*65 + c+3] = v.w;
        }
    }

    float mr[4], lr[4], acc[4][4];
    #pragma unroll
    for (int a = 0; a < 4; a++) {
        mr[a] = -1e30f; lr[a] = 0.f;
        #pragma unroll
        for (int c = 0; c < 4; c++) acc[a][c] = 0.f;
    }

    for (int j0 = 0; j0 <= i0; j0 += 64) {
        __syncthreads();

        const float* Kg = g_K + ((size_t)bh * Tdim + j0) * 64;
        const float* Vg = g_V + ((size_t)bh * Tdim + j0) * 64;
        const float* Pg = g_P + (size_t)bh * (Tdim * Tdim) + (size_t)j0 * Tdim + i0;
        #pragma unroll
        for (int p = 0; p < 4; p++) {
            int f4  = p * 256 + tid;
            int row = f4 >> 4;
            int c   = (f4 & 15) * 4;
            float4 kv = *(const float4*)(Kg + row * 64 + c);
            Ks[row*65 + c+0] = kv.x; Ks[row*65 + c+1] = kv.y;
            Ks[row*65 + c+2] = kv.z; Ks[row*65 + c+3] = kv.w;
            float4 vv = *(const float4*)(Vg + row * 64 + c);
            Vs[row*65 + c+0] = vv.x; Vs[row*65 + c+1] = vv.y;
            Vs[row*65 + c+2] = vv.z; Vs[row*65 + c+3] = vv.w;
            float4 pv = *(const float4*)(Pg + (size_t)row * Tdim + c);
            Ps[row*65 + c+0] = pv.x; Ps[row*65 + c+1] = pv.y;
            Ps[row*65 + c+2] = pv.z; Ps[row*65 + c+3] = pv.w;
        }
        __syncthreads();

        float s[4][4];
        #pragma unroll
        for (int a = 0; a < 4; a++)
            #pragma unroll
            for (int c = 0; c < 4; c++) s[a][c] = 0.f;

        #pragma unroll 4
        for (int d = 0; d < 64; d++) {
            float rq[4], rk[4];
            #pragma unroll
            for (int a = 0; a < 4; a++) rq[a] = Qs[(4*ty + a)*65 + d];
            #pragma unroll
            for (int c = 0; c < 4; c++) rk[c] = Ks[(4*tx + c)*65 + d];
            #pragma unroll
            for (int a = 0; a < 4; a++)
                #pragma unroll
                for (int c = 0; c < 4; c++)
                    s[a][c] = fmaf(rq[a], rk[c], s[a][c]);
        }

        const bool diag = (j0 == i0);
        #pragma unroll
        for (int a = 0; a < 4; a++) {
            #pragma unroll
            for (int c = 0; c < 4; c++) {
                float bias = Ps[(4*tx + c)*65 + (4*ty + a)];
                float v = (s[a][c] + bias) * 0.125f;
                if (diag && (4*tx + c) > (4*ty + a)) v = -1e30f;
                s[a][c] = v;
            }
        }

        __syncthreads();   // transpose-race fix: all bias reads before prob stores

        #pragma unroll
        for (int a = 0; a < 4; a++) {
            float rmax = s[a][0];
            rmax = fmaxf(rmax, s[a][1]);
            rmax = fmaxf(rmax, s[a][2]);
            rmax = fmaxf(rmax, s[a][3]);
            #pragma unroll
            for (int off = 8; off >= 1; off >>= 1)
                rmax = fmaxf(rmax, __shfl_xor_sync(0xffffffffu, rmax, off));
            float newm = fmaxf(mr[a], rmax);
            float corr = __expf(mr[a] - newm);
            float rsum = 0.f;
            #pragma unroll
            for (int c = 0; c < 4; c++) {
                s[a][c] = __expf(s[a][c] - newm);
                rsum += s[a][c];
            }
            #pragma unroll
            for (int off = 8; off >= 1; off >>= 1)
                rsum += __shfl_xor_sync(0xffffffffu, rsum, off);
            lr[a] = lr[a] * corr + rsum;
            mr[a] = newm;
            #pragma unroll
            for (int c = 0; c < 4; c++) acc[a][c] *= corr;
        }

        #pragma unroll
        for (int a = 0; a < 4; a++)
            #pragma unroll
            for (int c = 0; c < 4; c++)
                Ps[(4*ty + a)*65 + (4*tx + c)] = s[a][c];
        __syncthreads();

        #pragma unroll 4
        for (int jj = 0; jj < 64; jj++) {
            float rp[4], rv[4];
            #pragma unroll
            for (int a = 0; a < 4; a++) rp[a] = Ps[(4*ty + a)*65 + jj];
            #pragma unroll
            for (int c = 0; c < 4; c++) rv[c] = Vs[jj*65 + 4*tx + c];
            #pragma unroll
            for (int a = 0; a < 4; a++)
                #pragma unroll
                for (int c = 0; c < 4; c++)
                    acc[a][c] = fmaf(rp[a], rv[c], acc[a][c]);
        }
    }

    float* Yg = g_Y + ((size_t)b * Tdim + i0) * Cdim + h * 64;
    #pragma unroll
    for (int a = 0; a < 4; a++) {
        float inv = 1.f / lr[a];
        #pragma unroll
        for (int c = 0; c < 4; c++)
            Yg[(size_t)(4*ty + a) * Cdim + 4*tx + c] = acc[a][c] * inv;
    }
}

// ---------------------------------------------------------------------------
extern "C" void kernel_launch(void* const* d_in, const int* in_sizes, int n_in,
                              void* d_out, int out_size)
{
    const float* x      = (const float*)d_in[0];
    const float* W_attn = (const float*)d_in[1];
    const float* b_attn = (const float*)d_in[2];
    const float* W_proj = (const float*)d_in[3];
    const float* b_proj = (const float*)d_in[4];
    const float* rel    = (const float*)d_in[5];
    float* out = (float*)d_out;

    cudaFuncSetAttribute(gemm_bf16_kernel,
                         cudaFuncAttributeMaxDynamicSharedMemorySize, SMEM_GEMM);
    cudaFuncSetAttribute(flash_kernel,
                         cudaFuncAttributeMaxDynamicSharedMemorySize, 4 * 64 * 65 * 4);

    // prep: bf16 hi/lo splits (dsts resolved device-side)
    split_kernel<<<2048, 256>>>(x, 0, 4096 * 1024);
    transpose_split_kernel<<<dim3(3072/32, 1024/32), 256>>>(W_attn, 0, 1024, 3072);
    transpose_split_kernel<<<dim3(1024/32, 1024/32), 256>>>(W_proj, 1, 1024, 1024);

    // 1) QKV = x @ W_attn + b_attn (bf16 wmma x3), scattered into (b,h,t,d)
    gemm_bf16_kernel<<<dim3(24, 32), 256, SMEM_GEMM>>>(
        0, b_attn, nullptr, 1024, 0, 0);

    // 2) relative-position table
    pos_gemm_kernel<<<dim3(16, 16, BHdim), 256>>>(rel);

    // 3) fused causal flash attention
    flash_kernel<<<dim3(16, BHdim), 256, 4 * 64 * 65 * 4>>>(nullptr);

    // 4) out = Y @ W_proj + b_proj (bf16 wmma x3)
    split_kernel<<<2048, 256>>>(nullptr, 1, 4096 * 1024);
    gemm_bf16_kernel<<<dim3(8, 32), 256, SMEM_GEMM>>>(
        1, b_proj, out, 1024, 1, 1024);
}